// round 16
// baseline (speedup 1.0000x reference)
#include <cuda_runtime.h>
#include <cstdint>

#define BB 1024
#define TT 200
#define EE 128
#define HH 64
#define NTHREADS 512
#define GRID 148
#define NITEMS 2048

// ---- prepped weights (built once per launch by prep_kernel) ----
__device__ float4 g_bcF[2048];   // (W0b - W0c) in B-fragment order [k][p][lane]
__device__ float4 g_dF [2048];   // (W0d)       in B-fragment order
__device__ float  g_ac [8192];   // (W0a + W0c) natural [e][h] order

__global__ void prep_kernel(const float* __restrict__ W0) {
    const int i = blockIdx.x * blockDim.x + threadIdx.x;   // 8192 threads
    if (i < 8192) {
        const int e = i >> 6, h = i & 63;
        g_ac[i] = __ldg(W0 + e * 64 + h) + __ldg(W0 + (256 + e) * 64 + h);
    }
    if (i < 2048) {
        const int k = i >> 7;
        const int p = (i >> 5) & 3;
        const int l = i & 31;
        const int g = l >> 2, tg = l & 3;
        const int e0 = k * 8 + tg, e1 = e0 + 4;
        const int h0 = p * 16 + g, h1 = h0 + 8;
        float4 bc, dd;
        bc.x = __ldg(W0 + (128 + e0) * 64 + h0) - __ldg(W0 + (256 + e0) * 64 + h0);
        bc.y = __ldg(W0 + (128 + e1) * 64 + h0) - __ldg(W0 + (256 + e1) * 64 + h0);
        bc.z = __ldg(W0 + (128 + e0) * 64 + h1) - __ldg(W0 + (256 + e0) * 64 + h1);
        bc.w = __ldg(W0 + (128 + e1) * 64 + h1) - __ldg(W0 + (256 + e1) * 64 + h1);
        dd.x = __ldg(W0 + (384 + e0) * 64 + h0);
        dd.y = __ldg(W0 + (384 + e1) * 64 + h0);
        dd.z = __ldg(W0 + (384 + e0) * 64 + h1);
        dd.w = __ldg(W0 + (384 + e1) * 64 + h1);
        g_bcF[i] = bc;
        g_dF[i]  = dd;
    }
}

// ---- smem layout (float offsets), double buffered ----
#define SM_Q     0        // 2*128
#define SM_AW    256      // 2*128 (64 float2 each)
#define SM_APART 512      // 512 (A-partial scratch)
#define SM_EP    1024     // 256 (epilogue partials)
#define SM_BF    1280     // 2*8192
#define SM_AS    17664    // 2*14784 (112 rows * 132 floats each)
#define SMEM_FLOATS 47232
#define SMEM_BYTES (SMEM_FLOATS * 4)

__device__ __forceinline__ uint32_t smem_u32(const void* p) {
    uint32_t a;
    asm("{ .reg .u64 t; cvta.to.shared.u64 t, %1; cvt.u32.u64 %0, t; }" : "=r"(a) : "l"(p));
    return a;
}

__device__ __forceinline__ float to_tf32(float x) {
    float r; asm("cvt.rna.tf32.f32 %0, %1;" : "=f"(r) : "f"(x)); return r;
}

// 16B async copy; src_size=0 -> zero fill
__device__ __forceinline__ void cp16(uint32_t dst, const void* src, int src_size) {
    asm volatile("cp.async.cg.shared.global [%0], [%1], 16, %2;"
                 :: "r"(dst), "l"(src), "r"(src_size) : "memory");
}

__device__ __forceinline__ void mma8(float c[4], const uint32_t a[4],
                                     uint32_t b0, uint32_t b1) {
    asm volatile(
        "mma.sync.aligned.m16n8k8.row.col.f32.tf32.tf32.f32 "
        "{%0,%1,%2,%3}, {%4,%5,%6,%7}, {%8,%9}, {%0,%1,%2,%3};"
        : "+f"(c[0]), "+f"(c[1]), "+f"(c[2]), "+f"(c[3])
        : "r"(a[0]), "r"(a[1]), "r"(a[2]), "r"(a[3]), "r"(b0), "r"(b1));
}

__global__ void __launch_bounds__(NTHREADS, 1)
lau_mma_kernel(const float* __restrict__ query,
               const float* __restrict__ keys,
               const float* __restrict__ b0v,
               const float* __restrict__ W1,
               const float* __restrict__ b1v,
               float* __restrict__ out)
{
    extern __shared__ float sm[];
    const int tid = threadIdx.x;

    // ---- issue keys DMA for one item into buffer p ----
    auto issue_dma = [&](int item, int p) {
        const int b    = item >> 1;
        const int half = item & 1;
        const int t0   = half ? 96 : 0;
        const int rows = half ? 104 : 96;
        const int npad = (half ? 7 : 6) * 16;
        const float* kb = keys + ((size_t)b * TT + t0) * EE;
        const uint32_t base = smem_u32(sm + SM_AS + p * 14784);
        for (int idx = tid; idx < npad * 32; idx += NTHREADS) {
            const int r  = idx >> 5;
            const int c4 = idx & 31;
            const int rc = (r < rows) ? r : 0;
            cp16(base + (uint32_t)(r * 132 + c4 * 4) * 4,
                 (const float4*)(kb + rc * EE) + c4,
                 (r < rows) ? 16 : 0);
        }
        asm volatile("cp.async.commit_group;" ::: "memory");
    };

    // ---- build q, B fragments, A vector for one item into buffer p ----
    auto prepare = [&](int item, int p) {
        const int b = item >> 1;
        float*  q_s = sm + SM_Q  + p * 128;
        float2* aw  = (float2*)(sm + SM_AW + p * 128);
        float*  bf  = sm + SM_BF + p * 8192;
        float*  ap  = sm + SM_APART;

        if (tid < EE) q_s[tid] = __ldg(query + (size_t)b * EE + tid);
        __syncthreads();

        #pragma unroll 4
        for (int idx = tid; idx < 2048; idx += NTHREADS) {
            const float4 bc = __ldg(g_bcF + idx);
            const float4 dd = __ldg(g_dF  + idx);
            const int e0 = ((idx >> 7) << 3) | (idx & 3);
            const float q0 = q_s[e0], q1 = q_s[e0 + 4];
            float4 v;
            v.x = to_tf32(fmaf(q0, dd.x, bc.x));
            v.y = to_tf32(fmaf(q1, dd.y, bc.y));
            v.z = to_tf32(fmaf(q0, dd.z, bc.z));
            v.w = to_tf32(fmaf(q1, dd.w, bc.w));
            *(float4*)(bf + idx * 4) = v;
        }

        {
            const int h  = tid & 63;
            const int pp = tid >> 6;      // 0..7
            float s = 0.f;
            #pragma unroll 8
            for (int e = pp * 16; e < pp * 16 + 16; ++e)
                s = fmaf(q_s[e], __ldg(g_ac + e * 64 + h), s);
            ap[pp * 64 + h] = s;
        }
        __syncthreads();
        if (tid < HH) {
            float s = __ldg(b0v + tid);
            #pragma unroll
            for (int pp = 0; pp < 8; ++pp) s += ap[pp * 64 + tid];
            aw[tid] = make_float2(s, __ldg(W1 + tid));
        }
    };

    // ---- compute one item from buffer p, store result ----
    auto compute_store = [&](int item, int p) {
        const int b    = item >> 1;
        const int half = item & 1;
        const int t0   = half ? 96 : 0;
        const int rows = half ? 104 : 96;
        const int nblk = half ? 7 : 6;

        float*  as_ = sm + SM_AS + p * 14784;
        float*  bf  = sm + SM_BF + p * 8192;
        float2* aw  = (float2*)(sm + SM_AW + p * 128);
        float*  ep  = sm + SM_EP;

        const int wid = tid >> 5;
        const int lid = tid & 31;
        const int blk = wid >> 1;
        const int nh  = wid & 1;
        const int g   = lid >> 2;
        const int tg  = lid & 3;

        if (blk < nblk) {
            const int m0 = blk * 16;
            float acc[4][4];
            #pragma unroll
            for (int j = 0; j < 4; ++j)
                #pragma unroll
                for (int i = 0; i < 4; ++i) acc[j][i] = 0.f;

            const uint32_t* asu = (const uint32_t*)as_;
            const uint32_t* bfu = (const uint32_t*)bf;
            const int rowA = (m0 + g) * 132;

            #pragma unroll
            for (int k = 0; k < 16; ++k) {
                uint32_t a[4];
                const int col = k * 8 + tg;
                a[0] = asu[rowA + col];
                a[1] = asu[rowA + 8 * 132 + col];
                a[2] = asu[rowA + col + 4];
                a[3] = asu[rowA + 8 * 132 + col + 4];
                #pragma unroll
                for (int pp = 0; pp < 2; ++pp) {
                    const int pb = nh * 2 + pp;
                    const uint4 bv = *(const uint4*)(bfu + ((k * 4 + pb) * 32 + lid) * 4);
                    mma8(acc[2 * pp],     a, bv.x, bv.y);
                    mma8(acc[2 * pp + 1], a, bv.z, bv.w);
                }
            }

            float s0 = 0.f, s1 = 0.f;
            #pragma unroll
            for (int jj = 0; jj < 4; ++jj) {
                const int h = (nh * 4 + jj) * 8 + 2 * tg;
                const float2 w0 = aw[h];
                const float2 w1 = aw[h + 1];
                s0 = fmaf(fmaxf(acc[jj][0] + w0.x, 0.f), w0.y, s0);
                s0 = fmaf(fmaxf(acc[jj][1] + w1.x, 0.f), w1.y, s0);
                s1 = fmaf(fmaxf(acc[jj][2] + w0.x, 0.f), w0.y, s1);
                s1 = fmaf(fmaxf(acc[jj][3] + w1.x, 0.f), w1.y, s1);
            }
            s0 += __shfl_xor_sync(0xffffffffu, s0, 1);
            s0 += __shfl_xor_sync(0xffffffffu, s0, 2);
            s1 += __shfl_xor_sync(0xffffffffu, s1, 1);
            s1 += __shfl_xor_sync(0xffffffffu, s1, 2);
            if (tg == 0) {
                ep[nh * 128 + m0 + g]     = s0;
                ep[nh * 128 + m0 + g + 8] = s1;
            }
        }
        __syncthreads();
        if (tid < rows)
            out[(size_t)b * TT + t0 + tid] = ep[tid] + ep[128 + tid] + __ldg(b1v);
    };

    // ---- persistent pipeline over items ----
    int item = blockIdx.x;
    int p = 0;
    issue_dma(item, 0);
    prepare(item, 0);

    while (true) {
        const int nitem = item + GRID;
        if (nitem < NITEMS) {
            issue_dma(nitem, p ^ 1);
            prepare(nitem, p ^ 1);
            asm volatile("cp.async.wait_group 1;" ::: "memory");
        } else {
            asm volatile("cp.async.wait_group 0;" ::: "memory");
        }
        __syncthreads();

        compute_store(item, p);
        __syncthreads();   // buffers reusable

        if (nitem >= NITEMS) break;
        item = nitem;
        p ^= 1;
    }
}

extern "C" void kernel_launch(void* const* d_in, const int* in_sizes, int n_in,
                              void* d_out, int out_size)
{
    const float* query = (const float*)d_in[0];
    const float* keys  = (const float*)d_in[1];
    const float* W0    = (const float*)d_in[2];
    const float* b0    = (const float*)d_in[3];
    const float* W1    = (const float*)d_in[4];
    const float* b1    = (const float*)d_in[5];
    float* out = (float*)d_out;

    cudaFuncSetAttribute(lau_mma_kernel,
                         cudaFuncAttributeMaxDynamicSharedMemorySize, SMEM_BYTES);

    prep_kernel<<<32, 256>>>(W0);
    lau_mma_kernel<<<GRID, NTHREADS, SMEM_BYTES>>>(query, keys, b0, W1, b1, out);
}